// round 1
// baseline (speedup 1.0000x reference)
#include <cuda_runtime.h>
#include <math.h>

// Problem shape (fixed by the dataset)
#define BSZ 1024
#define DD  1024
#define LDCP 11008   // padded leading dim for logits (11003 -> 11008, 128B aligned)

// ---------------- scratch (device globals; no allocations allowed) ----------
__device__ float g_norm[2 * BSZ * DD];      // rows 0..1023 = vn, 1024..2047 = tn
__device__ float g_proj[2 * BSZ * DD];      // rows 0..1023 = vpt, 1024..2047 = tpv
__device__ float g_invW[LDCP];
__device__ float g_invW2[LDCP];
__device__ float g_logits1[2 * BSZ * LDCP]; // [2048, ldc] instance logits (x28, col-normalized)
__device__ float g_logits2[2 * BSZ * LDCP]; // [2048, ldc] cmpc logits
__device__ float g_sim[BSZ * BSZ];
__device__ float g_vp[BSZ * BSZ];
__device__ float g_tp[BSZ * BSZ];
__device__ float g_diag[BSZ];
__device__ int   g_cnt[256];
__device__ int   g_colmax[BSZ];             // float bits, values >= 0
__device__ double g_acc[6];                 // 0:ce1 1:ce2 2:ga 3:cmpm_v 4:cmpm_t 5:rowmax_sum
__device__ int   g_prec[2];

// ---------------- helpers ----------------------------------------------------
__device__ __forceinline__ float softplus_ref(float x) {
    // matches jnp.log1p(jnp.exp(x)) in f32; for large x exp overflows in ref? no:
    // max arg here is 40*(1-0.4)=24 -> exp fine. Guard anyway.
    return (x > 20.f) ? x : log1pf(expf(x));
}

// ---------------- init / histogram ------------------------------------------
__global__ void init_kernel() {
    int t = blockIdx.x * blockDim.x + threadIdx.x;
    if (t < 6)    g_acc[t] = 0.0;
    if (t < 2)    g_prec[t] = 0;
    if (t < 256)  g_cnt[t] = 0;
    if (t < BSZ)  g_colmax[t] = 0;
}

__global__ void hist_kernel(const int* __restrict__ labels) {
    int t = blockIdx.x * blockDim.x + threadIdx.x;
    if (t < BSZ) atomicAdd(&g_cnt[labels[t]], 1);
}

// ---------------- row normalize (vn, tn) -------------------------------------
__global__ void __launch_bounds__(256) normalize_kernel(const float* __restrict__ v,
                                                        const float* __restrict__ t) {
    __shared__ float red[256];
    int r = blockIdx.x;                     // 0..2047
    const float* src = (r < BSZ ? v : t) + (size_t)(r & (BSZ - 1)) * DD;
    float s = 0.f;
    for (int d = threadIdx.x; d < DD; d += 256) { float x = src[d]; s += x * x; }
    red[threadIdx.x] = s; __syncthreads();
    for (int st = 128; st > 0; st >>= 1) {
        if (threadIdx.x < st) red[threadIdx.x] += red[threadIdx.x + st];
        __syncthreads();
    }
    float inv = 1.f / sqrtf(red[0]);
    float* dst = g_norm + (size_t)r * DD;
    for (int d = threadIdx.x; d < DD; d += 256) dst[d] = src[d] * inv;
}

// ---------------- projections vpt, tpv ---------------------------------------
__global__ void __launch_bounds__(256) proj_kernel(const float* __restrict__ v,
                                                   const float* __restrict__ t) {
    __shared__ float r1[256], r2[256];
    int i = blockIdx.x;
    const float* vn = g_norm + (size_t)i * DD;
    const float* tn = g_norm + (size_t)(BSZ + i) * DD;
    const float* vi = v + (size_t)i * DD;
    const float* ti = t + (size_t)i * DD;
    float a = 0.f, b = 0.f;
    for (int d = threadIdx.x; d < DD; d += 256) { a += vi[d] * tn[d]; b += ti[d] * vn[d]; }
    r1[threadIdx.x] = a; r2[threadIdx.x] = b; __syncthreads();
    for (int st = 128; st > 0; st >>= 1) {
        if (threadIdx.x < st) { r1[threadIdx.x] += r1[threadIdx.x + st]; r2[threadIdx.x] += r2[threadIdx.x + st]; }
        __syncthreads();
    }
    float dv = r1[0], dt = r2[0];
    float* pv = g_proj + (size_t)i * DD;
    float* pt = g_proj + (size_t)(BSZ + i) * DD;
    for (int d = threadIdx.x; d < DD; d += 256) { pv[d] = dv * tn[d]; pt[d] = dt * vn[d]; }
}

// ---------------- column inverse norms of W / W2 ------------------------------
__global__ void colinv_kernel(const float* __restrict__ W, int which, int N) {
    int c = blockIdx.x * blockDim.x + threadIdx.x;
    if (c >= N) return;
    float s = 0.f;
    for (int d = 0; d < DD; d++) { float x = W[(size_t)d * N + c]; s += x * x; }
    float inv = 1.f / sqrtf(s);
    if (which) g_invW2[c] = inv; else g_invW[c] = inv;
}

// ---------------- NN SGEMM with column scaling --------------------------------
// C[m,n] = scale * invn[n] * sum_k A[m,k] * Bm[k,n];  A: [2048,1024] rm, Bm: [K,N] rm
__global__ void __launch_bounds__(256) sgemm_nn(const float* __restrict__ A,
                                                const float* __restrict__ Bm,
                                                const float* __restrict__ invn,
                                                float scale,
                                                float* __restrict__ Cm,
                                                int N, int K) {
    const int BK = 16;
    __shared__ float As[BK][128 + 4];
    __shared__ float Bs[BK][128 + 4];
    int tid = threadIdx.x;
    int r0 = blockIdx.y * 128, n0 = blockIdx.x * 128;
    int tRow = tid >> 4, tCol = tid & 15;
    float acc[8][8] = {};
    int aRow = tid >> 2, aCol = (tid & 3) * 4;

    for (int k0 = 0; k0 < K; k0 += BK) {
        float4 a0 = *(const float4*)(A + (size_t)(r0 + aRow) * K + k0 + aCol);
        float4 a1 = *(const float4*)(A + (size_t)(r0 + aRow + 64) * K + k0 + aCol);
        As[aCol + 0][aRow] = a0.x; As[aCol + 1][aRow] = a0.y;
        As[aCol + 2][aRow] = a0.z; As[aCol + 3][aRow] = a0.w;
        As[aCol + 0][aRow + 64] = a1.x; As[aCol + 1][aRow + 64] = a1.y;
        As[aCol + 2][aRow + 64] = a1.z; As[aCol + 3][aRow + 64] = a1.w;
#pragma unroll
        for (int i = 0; i < 8; i++) {
            int e = tid + i * 256;
            int br = e >> 7, bc = e & 127;
            int col = n0 + bc;
            Bs[br][bc] = (col < N) ? Bm[(size_t)(k0 + br) * N + col] : 0.f;
        }
        __syncthreads();
#pragma unroll
        for (int k = 0; k < BK; k++) {
            float a[8], b[8];
            *(float4*)&a[0] = *(const float4*)&As[k][tRow * 8];
            *(float4*)&a[4] = *(const float4*)&As[k][tRow * 8 + 4];
            *(float4*)&b[0] = *(const float4*)&Bs[k][tCol * 8];
            *(float4*)&b[4] = *(const float4*)&Bs[k][tCol * 8 + 4];
#pragma unroll
            for (int x = 0; x < 8; x++)
#pragma unroll
                for (int y = 0; y < 8; y++) acc[x][y] += a[x] * b[y];
        }
        __syncthreads();
    }
#pragma unroll
    for (int x = 0; x < 8; x++) {
        int row = r0 + tRow * 8 + x;
#pragma unroll
        for (int y = 0; y < 8; y++) {
            int col = n0 + tCol * 8 + y;
            if (col < N) Cm[(size_t)row * LDCP + col] = acc[x][y] * scale * invn[col];
        }
    }
}

// ---------------- NT SGEMM (1024x1024x1024): C[i,j] = dot(A[i,:], Bt[j,:]) ----
__global__ void __launch_bounds__(256) sgemm_nt(const float* __restrict__ A,
                                                const float* __restrict__ Bt,
                                                float* __restrict__ Cm) {
    const int BK = 16, K = 1024;
    __shared__ float As[BK][128 + 4];
    __shared__ float Bs[BK][128 + 4];
    int tid = threadIdx.x;
    int r0 = blockIdx.y * 128, n0 = blockIdx.x * 128;
    int tRow = tid >> 4, tCol = tid & 15;
    float acc[8][8] = {};
    int aRow = tid >> 2, aCol = (tid & 3) * 4;

    for (int k0 = 0; k0 < K; k0 += BK) {
        float4 a0 = *(const float4*)(A + (size_t)(r0 + aRow) * K + k0 + aCol);
        float4 a1 = *(const float4*)(A + (size_t)(r0 + aRow + 64) * K + k0 + aCol);
        As[aCol + 0][aRow] = a0.x; As[aCol + 1][aRow] = a0.y;
        As[aCol + 2][aRow] = a0.z; As[aCol + 3][aRow] = a0.w;
        As[aCol + 0][aRow + 64] = a1.x; As[aCol + 1][aRow + 64] = a1.y;
        As[aCol + 2][aRow + 64] = a1.z; As[aCol + 3][aRow + 64] = a1.w;
#pragma unroll
        for (int i = 0; i < 8; i++) {
            int e = tid + i * 256;
            int bn = e >> 4, bk = e & 15;
            Bs[bk][bn] = Bt[(size_t)(n0 + bn) * K + k0 + bk];
        }
        __syncthreads();
#pragma unroll
        for (int k = 0; k < BK; k++) {
            float a[8], b[8];
            *(float4*)&a[0] = *(const float4*)&As[k][tRow * 8];
            *(float4*)&a[4] = *(const float4*)&As[k][tRow * 8 + 4];
            *(float4*)&b[0] = *(const float4*)&Bs[k][tCol * 8];
            *(float4*)&b[4] = *(const float4*)&Bs[k][tCol * 8 + 4];
#pragma unroll
            for (int x = 0; x < 8; x++)
#pragma unroll
                for (int y = 0; y < 8; y++) acc[x][y] += a[x] * b[y];
        }
        __syncthreads();
    }
#pragma unroll
    for (int x = 0; x < 8; x++) {
        int row = r0 + tRow * 8 + x;
#pragma unroll
        for (int y = 0; y < 8; y++) {
            int col = n0 + tCol * 8 + y;
            Cm[(size_t)row * BSZ + col] = acc[x][y];
        }
    }
}

// ---------------- diag extract ------------------------------------------------
__global__ void diag_kernel() {
    int i = blockIdx.x * blockDim.x + threadIdx.x;
    if (i < BSZ) g_diag[i] = g_sim[(size_t)i * BSZ + i];
}

// ---------------- CE row reductions over C=11003 ------------------------------
__global__ void __launch_bounds__(256) reduce_ce_kernel(const int* __restrict__ labels, int C) {
    __shared__ float shf[256];
    __shared__ int   shi[256];
    int r = blockIdx.x;                 // 0..4095
    int tid = threadIdx.x;
    const float* Lr = (r < 2048 ? g_logits1 : g_logits2) + (size_t)(r & 2047) * LDCP;

    float mx = -1e30f; int mi = 0;
    for (int j = tid; j < C; j += 256) {
        float v = Lr[j];
        if (v > mx || (v == mx && j < mi)) { mx = v; mi = j; }
    }
    shf[tid] = mx; shi[tid] = mi; __syncthreads();
    for (int s = 128; s > 0; s >>= 1) {
        if (tid < s) {
            float o = shf[tid + s]; int oi = shi[tid + s];
            if (o > shf[tid] || (o == shf[tid] && oi < shi[tid])) { shf[tid] = o; shi[tid] = oi; }
        }
        __syncthreads();
    }
    float MX = shf[0]; int MI = shi[0];
    __syncthreads();

    float s = 0.f;
    for (int j = tid; j < C; j += 256) s += expf(Lr[j] - MX);
    shf[tid] = s; __syncthreads();
    for (int st = 128; st > 0; st >>= 1) {
        if (tid < st) shf[tid] += shf[tid + st];
        __syncthreads();
    }
    if (tid == 0) {
        int lab = labels[r & (BSZ - 1)];
        float loss = logf(shf[0]) + MX - Lr[lab];
        if (r < 2048) {
            atomicAdd(&g_acc[0], (double)loss);
        } else {
            atomicAdd(&g_acc[1], (double)loss);
            if (MI == lab) atomicAdd(&g_prec[((r & 2047) < BSZ) ? 0 : 1], 1);
        }
    }
}

// ---------------- pairwise losses (global-align, cmpm, MH) --------------------
__global__ void __launch_bounds__(256) pair_kernel(const int* __restrict__ labels) {
    __shared__ float s_sim[BSZ], s_vp[BSZ], s_tp[BSZ];
    __shared__ float r1[256], r2[256];
    int i = blockIdx.x, tid = threadIdx.x;
    int li = labels[i];
    float dii = g_diag[i];

    for (int j = tid; j < BSZ; j += 256) {
        s_sim[j] = g_sim[(size_t)i * BSZ + j];
        s_vp[j]  = g_vp[(size_t)i * BSZ + j];
        s_tp[j]  = g_tp[(size_t)i * BSZ + j];
    }
    __syncthreads();

    float mv = -1e30f, mt = -1e30f;
    for (int j = tid; j < BSZ; j += 256) { mv = fmaxf(mv, s_vp[j]); mt = fmaxf(mt, s_tp[j]); }
    r1[tid] = mv; r2[tid] = mt; __syncthreads();
    for (int s = 128; s > 0; s >>= 1) {
        if (tid < s) { r1[tid] = fmaxf(r1[tid], r1[tid + s]); r2[tid] = fmaxf(r2[tid], r2[tid + s]); }
        __syncthreads();
    }
    float MV = r1[0], MT = r2[0];
    __syncthreads();

    float sv = 0.f, st = 0.f;
    for (int j = tid; j < BSZ; j += 256) { sv += expf(s_vp[j] - MV); st += expf(s_tp[j] - MT); }
    r1[tid] = sv; r2[tid] = st; __syncthreads();
    for (int s = 128; s > 0; s >>= 1) {
        if (tid < s) { r1[tid] += r1[tid + s]; r2[tid] += r2[tid + s]; }
        __syncthreads();
    }
    float LSV = logf(r1[0]), LST = logf(r2[0]);
    __syncthreads();

    float ga = 0.f, cv = 0.f, ct = 0.f, rmax = 0.f;
    for (int j = tid; j < BSZ; j += 256) {
        float sij = s_sim[j];
        int lj = labels[j];
        bool m = (lj == li);
        // global align
        ga += m ? softplus_ref(-10.f * (sij - 0.6f)) : softplus_ref(40.f * (sij - 0.4f));
        // cmpm: mask_norm[i,j] = mask/sqrt(cnt[label_j]); log(x + 1e-8)
        float invrn = rsqrtf((float)g_cnt[lj]);
        float lmn = logf((m ? invrn : 0.f) + 1e-8f);
        float lv = s_vp[j] - MV - LSV;
        cv += expf(lv) * (lv - lmn);
        float lt = s_tp[j] - MT - LST;
        ct += expf(lt) * (lt - lmn);
        // MH hinge
        if (!m) {
            float cs = 0.2f + sij - dii;
            rmax = fmaxf(rmax, cs);
            float ci = 0.2f + sij - g_diag[j];
            if (ci > 0.f) atomicMax(&g_colmax[j], __float_as_int(ci));
        }
    }
    // reduce ga
    r1[tid] = ga; __syncthreads();
    for (int s = 128; s > 0; s >>= 1) { if (tid < s) r1[tid] += r1[tid + s]; __syncthreads(); }
    if (tid == 0) atomicAdd(&g_acc[2], (double)r1[0]);
    __syncthreads();
    // reduce cmpm_v
    r1[tid] = cv; __syncthreads();
    for (int s = 128; s > 0; s >>= 1) { if (tid < s) r1[tid] += r1[tid + s]; __syncthreads(); }
    if (tid == 0) atomicAdd(&g_acc[3], (double)r1[0]);
    __syncthreads();
    // reduce cmpm_t
    r1[tid] = ct; __syncthreads();
    for (int s = 128; s > 0; s >>= 1) { if (tid < s) r1[tid] += r1[tid + s]; __syncthreads(); }
    if (tid == 0) atomicAdd(&g_acc[4], (double)r1[0]);
    __syncthreads();
    // reduce row max (values >= 0)
    r1[tid] = rmax; __syncthreads();
    for (int s = 128; s > 0; s >>= 1) { if (tid < s) r1[tid] = fmaxf(r1[tid], r1[tid + s]); __syncthreads(); }
    if (tid == 0) atomicAdd(&g_acc[5], (double)r1[0]);
}

// ---------------- finalize ----------------------------------------------------
__global__ void __launch_bounds__(256) finalize_kernel(float* __restrict__ out) {
    __shared__ float red[256];
    int tid = threadIdx.x;
    float s = 0.f;
    for (int j = tid; j < BSZ; j += 256) s += __int_as_float(g_colmax[j]);
    red[tid] = s; __syncthreads();
    for (int st = 128; st > 0; st >>= 1) { if (tid < st) red[tid] += red[tid + st]; __syncthreads(); }
    if (tid == 0) {
        float colsum = red[0];
        out[0] = (float)(g_acc[0] / 1024.0);                    // instance_loss
        out[1] = (float)(2.0 * g_acc[2] / 1024.0);              // global_align_loss
        out[2] = (float)(g_acc[1] / 1024.0);                    // cmpc_loss
        out[3] = (float)((g_acc[3] + g_acc[4]) / 1024.0);       // cmpm_loss
        out[4] = (float)(g_acc[5] + (double)colsum);            // mh_loss
        out[5] = (float)g_prec[0] / 1024.f;                     // visual_prec
        out[6] = (float)g_prec[1] / 1024.f;                     // textual_prec
    }
}

// ---------------- launch ------------------------------------------------------
extern "C" void kernel_launch(void* const* d_in, const int* in_sizes, int n_in,
                              void* d_out, int out_size) {
    const float* v      = (const float*)d_in[0];
    const float* t      = (const float*)d_in[1];
    const float* W      = (const float*)d_in[2];
    const float* W2     = (const float*)d_in[3];
    const int*   labels = (const int*)d_in[4];
    float* out = (float*)d_out;
    int C = in_sizes[2] / DD;   // 11003

    float *p_norm, *p_proj, *p_invW, *p_invW2, *p_l1, *p_l2, *p_sim, *p_vp, *p_tp;
    cudaGetSymbolAddress((void**)&p_norm,  g_norm);
    cudaGetSymbolAddress((void**)&p_proj,  g_proj);
    cudaGetSymbolAddress((void**)&p_invW,  g_invW);
    cudaGetSymbolAddress((void**)&p_invW2, g_invW2);
    cudaGetSymbolAddress((void**)&p_l1,    g_logits1);
    cudaGetSymbolAddress((void**)&p_l2,    g_logits2);
    cudaGetSymbolAddress((void**)&p_sim,   g_sim);
    cudaGetSymbolAddress((void**)&p_vp,    g_vp);
    cudaGetSymbolAddress((void**)&p_tp,    g_tp);

    init_kernel<<<4, 256>>>();
    hist_kernel<<<4, 256>>>(labels);
    normalize_kernel<<<2 * BSZ, 256>>>(v, t);
    proj_kernel<<<BSZ, 256>>>(v, t);
    colinv_kernel<<<(C + 255) / 256, 256>>>(W, 0, C);
    colinv_kernel<<<(C + 255) / 256, 256>>>(W2, 1, C);

    dim3 g1((C + 127) / 128, 2 * BSZ / 128);
    sgemm_nn<<<g1, 256>>>(p_norm, W,  p_invW,  28.f, p_l1, C, DD);
    sgemm_nn<<<g1, 256>>>(p_proj, W2, p_invW2, 1.f,  p_l2, C, DD);

    dim3 g2(BSZ / 128, BSZ / 128);
    sgemm_nt<<<g2, 256>>>(p_norm,               p_norm + BSZ * DD, p_sim); // vn @ tn^T
    sgemm_nt<<<g2, 256>>>(v,                    p_norm + BSZ * DD, p_vp);  // visual @ tn^T
    sgemm_nt<<<g2, 256>>>(t,                    p_norm,            p_tp);  // textual @ vn^T

    diag_kernel<<<4, 256>>>();
    reduce_ce_kernel<<<4096, 256>>>(labels, C);
    pair_kernel<<<BSZ, 256>>>(labels);
    finalize_kernel<<<1, 256>>>(out);
}

// round 3
// speedup vs baseline: 1.2926x; 1.2926x over previous
#include <cuda_runtime.h>
#include <math.h>
#include <stdint.h>

// Problem shape (fixed by the dataset)
#define BSZ 1024
#define DD  1024
#define LDCP 11008   // padded leading dim for logits (11003 -> 11008)

// ---------------- scratch (device globals; no allocations allowed) ----------
__device__ float g_norm[2 * BSZ * DD];      // rows 0..1023 = vn, 1024..2047 = tn
__device__ float g_proj[2 * BSZ * DD];      // rows 0..1023 = vpt, 1024..2047 = tpv
__device__ float g_invW[LDCP];
__device__ float g_invW2[LDCP];
__device__ float g_logits1[2 * BSZ * LDCP];
__device__ float g_logits2[2 * BSZ * LDCP];
__device__ float g_sim[BSZ * BSZ];
__device__ float g_vp[BSZ * BSZ];
__device__ float g_tp[BSZ * BSZ];
__device__ float g_diag[BSZ];
__device__ int   g_cnt[256];
__device__ int   g_colmax[BSZ];             // float bits, values >= 0
__device__ double g_acc[6];                 // 0:ce1 1:ce2 2:ga 3:cmpm_v 4:cmpm_t 5:rowmax_sum
__device__ int   g_prec[2];

// ---------------- helpers ----------------------------------------------------
__device__ __forceinline__ float softplus_ref(float x) {
    return (x > 20.f) ? x : log1pf(__expf(x));
}

__device__ __forceinline__ void split_tf32(float x, uint32_t& hi, uint32_t& lo) {
    uint32_t h;
    asm("cvt.rna.tf32.f32 %0, %1;" : "=r"(h) : "f"(x));
    float l = x - __uint_as_float(h);
    uint32_t lw;
    asm("cvt.rna.tf32.f32 %0, %1;" : "=r"(lw) : "f"(l));
    hi = h; lo = lw;
}

__device__ __forceinline__ void mma_tf32(float* c, const uint32_t* a, const uint32_t* b) {
    asm volatile(
        "mma.sync.aligned.m16n8k8.row.col.f32.tf32.tf32.f32 "
        "{%0,%1,%2,%3}, {%4,%5,%6,%7}, {%8,%9}, {%0,%1,%2,%3};"
        : "+f"(c[0]), "+f"(c[1]), "+f"(c[2]), "+f"(c[3])
        : "r"(a[0]), "r"(a[1]), "r"(a[2]), "r"(a[3]), "r"(b[0]), "r"(b[1]));
}

// ---------------- init / histogram ------------------------------------------
__global__ void init_kernel() {
    int t = blockIdx.x * blockDim.x + threadIdx.x;
    if (t < 6)    g_acc[t] = 0.0;
    if (t < 2)    g_prec[t] = 0;
    if (t < 256)  g_cnt[t] = 0;
    if (t < BSZ)  g_colmax[t] = 0;
}

__global__ void hist_kernel(const int* __restrict__ labels) {
    int t = blockIdx.x * blockDim.x + threadIdx.x;
    if (t < BSZ) atomicAdd(&g_cnt[labels[t]], 1);
}

// ---------------- row normalize (vn, tn) -------------------------------------
__global__ void __launch_bounds__(256) normalize_kernel(const float* __restrict__ v,
                                                        const float* __restrict__ t) {
    __shared__ float red[256];
    int r = blockIdx.x;                     // 0..2047
    const float* src = (r < BSZ ? v : t) + (size_t)(r & (BSZ - 1)) * DD;
    float s = 0.f;
    for (int d = threadIdx.x; d < DD; d += 256) { float x = src[d]; s += x * x; }
    red[threadIdx.x] = s; __syncthreads();
    for (int st = 128; st > 0; st >>= 1) {
        if (threadIdx.x < st) red[threadIdx.x] += red[threadIdx.x + st];
        __syncthreads();
    }
    float inv = 1.f / sqrtf(red[0]);
    float* dst = g_norm + (size_t)r * DD;
    for (int d = threadIdx.x; d < DD; d += 256) dst[d] = src[d] * inv;
}

// ---------------- projections vpt, tpv ---------------------------------------
__global__ void __launch_bounds__(256) proj_kernel(const float* __restrict__ v,
                                                   const float* __restrict__ t) {
    __shared__ float r1[256], r2[256];
    int i = blockIdx.x;
    const float* vn = g_norm + (size_t)i * DD;
    const float* tn = g_norm + (size_t)(BSZ + i) * DD;
    const float* vi = v + (size_t)i * DD;
    const float* ti = t + (size_t)i * DD;
    float a = 0.f, b = 0.f;
    for (int d = threadIdx.x; d < DD; d += 256) { a += vi[d] * tn[d]; b += ti[d] * vn[d]; }
    r1[threadIdx.x] = a; r2[threadIdx.x] = b; __syncthreads();
    for (int st = 128; st > 0; st >>= 1) {
        if (threadIdx.x < st) { r1[threadIdx.x] += r1[threadIdx.x + st]; r2[threadIdx.x] += r2[threadIdx.x + st]; }
        __syncthreads();
    }
    float dv = r1[0], dt = r2[0];
    float* pv = g_proj + (size_t)i * DD;
    float* pt = g_proj + (size_t)(BSZ + i) * DD;
    for (int d = threadIdx.x; d < DD; d += 256) { pv[d] = dv * tn[d]; pt[d] = dt * vn[d]; }
}

// ---------------- column inverse norms of W / W2 ------------------------------
__global__ void colinv_kernel(const float* __restrict__ W, int which, int N) {
    int c = blockIdx.x * blockDim.x + threadIdx.x;
    if (c >= N) return;
    float s = 0.f;
    for (int d = 0; d < DD; d++) { float x = W[(size_t)d * N + c]; s += x * x; }
    float inv = 1.f / sqrtf(s);
    if (which) g_invW2[c] = inv; else g_invW[c] = inv;
}

// =====================================================================
// Tensor-core NN GEMM with 3xTF32 split:
//   C[m,n] = scale*invn[n] * sum_k A[m,k]*Bm[k,n]
// A: [2048,1024] rm;  Bm: [1024,N] rm;  C stored with ldc=LDCP
// BM=128, BN=128, BK=16, 256 thr, warp tile 64x32
// =====================================================================
__global__ void __launch_bounds__(256, 2) gemm_nn_tc(const float* __restrict__ A,
                                                     const float* __restrict__ Bm,
                                                     const float* __restrict__ invn,
                                                     float scale,
                                                     float* __restrict__ Cm,
                                                     int N) {
    __shared__ float As[128][20];
    __shared__ float Bs[16][136];
    const int tid = threadIdx.x;
    const int lane = tid & 31, g = lane >> 2, tig = lane & 3;
    const int warpId = tid >> 5;
    const int warpM = (warpId & 1) * 64;
    const int warpN = (warpId >> 1) * 32;
    const int m0 = blockIdx.y * 128, n0 = blockIdx.x * 128;

    const int ar = tid >> 2;            // 0..63
    const int ac = (tid & 3) * 4;

    float acc[4][4][4];
#pragma unroll
    for (int i = 0; i < 4; i++)
#pragma unroll
        for (int j = 0; j < 4; j++)
#pragma unroll
            for (int k = 0; k < 4; k++) acc[i][j][k] = 0.f;

    for (int k0 = 0; k0 < 1024; k0 += 16) {
        float4 a0 = *(const float4*)(A + (size_t)(m0 + ar) * 1024 + k0 + ac);
        float4 a1 = *(const float4*)(A + (size_t)(m0 + ar + 64) * 1024 + k0 + ac);
        As[ar][ac + 0] = a0.x; As[ar][ac + 1] = a0.y; As[ar][ac + 2] = a0.z; As[ar][ac + 3] = a0.w;
        As[ar + 64][ac + 0] = a1.x; As[ar + 64][ac + 1] = a1.y; As[ar + 64][ac + 2] = a1.z; As[ar + 64][ac + 3] = a1.w;
#pragma unroll
        for (int i = 0; i < 8; i++) {
            int e = tid + i * 256;
            int k = e >> 7, n = e & 127;
            int col = n0 + n;
            Bs[k][n] = (col < N) ? __ldg(Bm + (size_t)(k0 + k) * N + col) : 0.f;
        }
        __syncthreads();

#pragma unroll
        for (int ks = 0; ks < 2; ks++) {
            uint32_t bhi[8], blo[8];
#pragma unroll
            for (int nt = 0; nt < 4; nt++) {
                float b0 = Bs[ks * 8 + tig][warpN + nt * 8 + g];
                float b1 = Bs[ks * 8 + tig + 4][warpN + nt * 8 + g];
                split_tf32(b0, bhi[2 * nt], blo[2 * nt]);
                split_tf32(b1, bhi[2 * nt + 1], blo[2 * nt + 1]);
            }
#pragma unroll
            for (int mt = 0; mt < 4; mt++) {
                uint32_t ahi[4], alo[4];
                float a_0 = As[warpM + mt * 16 + g][ks * 8 + tig];
                float a_1 = As[warpM + mt * 16 + g + 8][ks * 8 + tig];
                float a_2 = As[warpM + mt * 16 + g][ks * 8 + tig + 4];
                float a_3 = As[warpM + mt * 16 + g + 8][ks * 8 + tig + 4];
                split_tf32(a_0, ahi[0], alo[0]);
                split_tf32(a_1, ahi[1], alo[1]);
                split_tf32(a_2, ahi[2], alo[2]);
                split_tf32(a_3, ahi[3], alo[3]);
#pragma unroll
                for (int nt = 0; nt < 4; nt++) {
                    mma_tf32(acc[mt][nt], ahi, bhi + 2 * nt);
                    mma_tf32(acc[mt][nt], ahi, blo + 2 * nt);
                    mma_tf32(acc[mt][nt], alo, bhi + 2 * nt);
                }
            }
        }
        __syncthreads();
    }

#pragma unroll
    for (int mt = 0; mt < 4; mt++) {
#pragma unroll
        for (int nt = 0; nt < 4; nt++) {
            int r = m0 + warpM + mt * 16 + g;
            int c = n0 + warpN + nt * 8 + 2 * tig;
            if (c < N) {
                float sc = scale * invn[c];
                Cm[(size_t)r * LDCP + c] = acc[mt][nt][0] * sc;
                Cm[(size_t)(r + 8) * LDCP + c] = acc[mt][nt][2] * sc;
            }
            if (c + 1 < N) {
                float sc = scale * invn[c + 1];
                Cm[(size_t)r * LDCP + c + 1] = acc[mt][nt][1] * sc;
                Cm[(size_t)(r + 8) * LDCP + c + 1] = acc[mt][nt][3] * sc;
            }
        }
    }
}

// =====================================================================
// Tensor-core NT GEMM (1024x1024x1024), 3xTF32:
//   C[i,j] = dot(A[i,:], Bt[j,:])
// z selects: 0: sim = vn@tn^T   1: vp = v@tn^T   2: tp = t@vn^T
// =====================================================================
__global__ void __launch_bounds__(256, 2) gemm_nt_tc(const float* __restrict__ v,
                                                     const float* __restrict__ t) {
    __shared__ float As[128][20];
    __shared__ float Bs[16][136];
    const float* A; const float* Bt; float* Cm;
    if (blockIdx.z == 0)      { A = g_norm;           Bt = g_norm + BSZ * DD; Cm = g_sim; }
    else if (blockIdx.z == 1) { A = v;                Bt = g_norm + BSZ * DD; Cm = g_vp; }
    else                      { A = t;                Bt = g_norm;            Cm = g_tp; }

    const int tid = threadIdx.x;
    const int lane = tid & 31, g = lane >> 2, tig = lane & 3;
    const int warpId = tid >> 5;
    const int warpM = (warpId & 1) * 64;
    const int warpN = (warpId >> 1) * 32;
    const int m0 = blockIdx.y * 128, n0 = blockIdx.x * 128;

    const int ar = tid >> 2;
    const int ac = (tid & 3) * 4;

    float acc[4][4][4];
#pragma unroll
    for (int i = 0; i < 4; i++)
#pragma unroll
        for (int j = 0; j < 4; j++)
#pragma unroll
            for (int k = 0; k < 4; k++) acc[i][j][k] = 0.f;

    for (int k0 = 0; k0 < 1024; k0 += 16) {
        float4 a0 = *(const float4*)(A + (size_t)(m0 + ar) * 1024 + k0 + ac);
        float4 a1 = *(const float4*)(A + (size_t)(m0 + ar + 64) * 1024 + k0 + ac);
        As[ar][ac + 0] = a0.x; As[ar][ac + 1] = a0.y; As[ar][ac + 2] = a0.z; As[ar][ac + 3] = a0.w;
        As[ar + 64][ac + 0] = a1.x; As[ar + 64][ac + 1] = a1.y; As[ar + 64][ac + 2] = a1.z; As[ar + 64][ac + 3] = a1.w;
#pragma unroll
        for (int i = 0; i < 2; i++) {
            int e4 = tid + i * 256;     // 0..511
            int n = e4 >> 2;            // 0..127
            int kq = (e4 & 3) * 4;      // 0,4,8,12
            float4 bv = *(const float4*)(Bt + (size_t)(n0 + n) * 1024 + k0 + kq);
            Bs[kq + 0][n] = bv.x; Bs[kq + 1][n] = bv.y; Bs[kq + 2][n] = bv.z; Bs[kq + 3][n] = bv.w;
        }
        __syncthreads();

#pragma unroll
        for (int ks = 0; ks < 2; ks++) {
            uint32_t bhi[8], blo[8];
#pragma unroll
            for (int nt = 0; nt < 4; nt++) {
                float b0 = Bs[ks * 8 + tig][warpN + nt * 8 + g];
                float b1 = Bs[ks * 8 + tig + 4][warpN + nt * 8 + g];
                split_tf32(b0, bhi[2 * nt], blo[2 * nt]);
                split_tf32(b1, bhi[2 * nt + 1], blo[2 * nt + 1]);
            }
#pragma unroll
            for (int mt = 0; mt < 4; mt++) {
                uint32_t ahi[4], alo[4];
                float a_0 = As[warpM + mt * 16 + g][ks * 8 + tig];
                float a_1 = As[warpM + mt * 16 + g + 8][ks * 8 + tig];
                float a_2 = As[warpM + mt * 16 + g][ks * 8 + tig + 4];
                float a_3 = As[warpM + mt * 16 + g + 8][ks * 8 + tig + 4];
                split_tf32(a_0, ahi[0], alo[0]);
                split_tf32(a_1, ahi[1], alo[1]);
                split_tf32(a_2, ahi[2], alo[2]);
                split_tf32(a_3, ahi[3], alo[3]);
#pragma unroll
                for (int nt = 0; nt < 4; nt++) {
                    mma_tf32(acc[mt][nt], ahi, bhi + 2 * nt);
                    mma_tf32(acc[mt][nt], ahi, blo + 2 * nt);
                    mma_tf32(acc[mt][nt], alo, bhi + 2 * nt);
                }
            }
        }
        __syncthreads();
    }

#pragma unroll
    for (int mt = 0; mt < 4; mt++) {
#pragma unroll
        for (int nt = 0; nt < 4; nt++) {
            int r = m0 + warpM + mt * 16 + g;
            int c = n0 + warpN + nt * 8 + 2 * tig;
            Cm[(size_t)r * BSZ + c]           = acc[mt][nt][0];
            Cm[(size_t)r * BSZ + c + 1]       = acc[mt][nt][1];
            Cm[(size_t)(r + 8) * BSZ + c]     = acc[mt][nt][2];
            Cm[(size_t)(r + 8) * BSZ + c + 1] = acc[mt][nt][3];
        }
    }
}

// ---------------- diag extract ------------------------------------------------
__global__ void diag_kernel() {
    int i = blockIdx.x * blockDim.x + threadIdx.x;
    if (i < BSZ) g_diag[i] = g_sim[(size_t)i * BSZ + i];
}

// ---------------- CE row reductions over C=11003 ------------------------------
__global__ void __launch_bounds__(256) reduce_ce_kernel(const int* __restrict__ labels, int C) {
    __shared__ float shf[256];
    __shared__ int   shi[256];
    int r = blockIdx.x;                 // 0..4095
    int tid = threadIdx.x;
    const float* Lr = (r < 2048 ? g_logits1 : g_logits2) + (size_t)(r & 2047) * LDCP;

    float mx = -1e30f; int mi = 0;
    for (int j = tid; j < C; j += 256) {
        float v = Lr[j];
        if (v > mx || (v == mx && j < mi)) { mx = v; mi = j; }
    }
    shf[tid] = mx; shi[tid] = mi; __syncthreads();
    for (int s = 128; s > 0; s >>= 1) {
        if (tid < s) {
            float o = shf[tid + s]; int oi = shi[tid + s];
            if (o > shf[tid] || (o == shf[tid] && oi < shi[tid])) { shf[tid] = o; shi[tid] = oi; }
        }
        __syncthreads();
    }
    float MX = shf[0]; int MI = shi[0];
    __syncthreads();

    float s = 0.f;
    for (int j = tid; j < C; j += 256) s += __expf(Lr[j] - MX);
    shf[tid] = s; __syncthreads();
    for (int st = 128; st > 0; st >>= 1) {
        if (tid < st) shf[tid] += shf[tid + st];
        __syncthreads();
    }
    if (tid == 0) {
        int lab = labels[r & (BSZ - 1)];
        float loss = logf(shf[0]) + MX - Lr[lab];
        if (r < 2048) {
            atomicAdd(&g_acc[0], (double)loss);
        } else {
            atomicAdd(&g_acc[1], (double)loss);
            if (MI == lab) atomicAdd(&g_prec[((r & 2047) < BSZ) ? 0 : 1], 1);
        }
    }
}

// ---------------- pairwise losses (global-align, cmpm, MH) --------------------
__global__ void __launch_bounds__(256) pair_kernel(const int* __restrict__ labels) {
    __shared__ float s_sim[BSZ], s_vp[BSZ], s_tp[BSZ];
    __shared__ float r1[256], r2[256];
    int i = blockIdx.x, tid = threadIdx.x;
    int li = labels[i];
    float dii = g_diag[i];

    for (int j = tid; j < BSZ; j += 256) {
        s_sim[j] = g_sim[(size_t)i * BSZ + j];
        s_vp[j]  = g_vp[(size_t)i * BSZ + j];
        s_tp[j]  = g_tp[(size_t)i * BSZ + j];
    }
    __syncthreads();

    float mv = -1e30f, mt = -1e30f;
    for (int j = tid; j < BSZ; j += 256) { mv = fmaxf(mv, s_vp[j]); mt = fmaxf(mt, s_tp[j]); }
    r1[tid] = mv; r2[tid] = mt; __syncthreads();
    for (int s = 128; s > 0; s >>= 1) {
        if (tid < s) { r1[tid] = fmaxf(r1[tid], r1[tid + s]); r2[tid] = fmaxf(r2[tid], r2[tid + s]); }
        __syncthreads();
    }
    float MV = r1[0], MT = r2[0];
    __syncthreads();

    float sv = 0.f, st = 0.f;
    for (int j = tid; j < BSZ; j += 256) { sv += __expf(s_vp[j] - MV); st += __expf(s_tp[j] - MT); }
    r1[tid] = sv; r2[tid] = st; __syncthreads();
    for (int s = 128; s > 0; s >>= 1) {
        if (tid < s) { r1[tid] += r1[tid + s]; r2[tid] += r2[tid + s]; }
        __syncthreads();
    }
    float LSV = logf(r1[0]), LST = logf(r2[0]);
    __syncthreads();

    float ga = 0.f, cv = 0.f, ct = 0.f, rmax = 0.f;
    for (int j = tid; j < BSZ; j += 256) {
        float sij = s_sim[j];
        int lj = labels[j];
        bool m = (lj == li);
        ga += m ? softplus_ref(-10.f * (sij - 0.6f)) : softplus_ref(40.f * (sij - 0.4f));
        float invrn = rsqrtf((float)g_cnt[lj]);
        float lmn = logf((m ? invrn : 0.f) + 1e-8f);
        float lv = s_vp[j] - MV - LSV;
        cv += __expf(lv) * (lv - lmn);
        float lt = s_tp[j] - MT - LST;
        ct += __expf(lt) * (lt - lmn);
        if (!m) {
            float cs = 0.2f + sij - dii;
            rmax = fmaxf(rmax, cs);
            float ci = 0.2f + sij - g_diag[j];
            if (ci > 0.f) atomicMax(&g_colmax[j], __float_as_int(ci));
        }
    }
    r1[tid] = ga; __syncthreads();
    for (int s = 128; s > 0; s >>= 1) { if (tid < s) r1[tid] += r1[tid + s]; __syncthreads(); }
    if (tid == 0) atomicAdd(&g_acc[2], (double)r1[0]);
    __syncthreads();
    r1[tid] = cv; __syncthreads();
    for (int s = 128; s > 0; s >>= 1) { if (tid < s) r1[tid] += r1[tid + s]; __syncthreads(); }
    if (tid == 0) atomicAdd(&g_acc[3], (double)r1[0]);
    __syncthreads();
    r1[tid] = ct; __syncthreads();
    for (int s = 128; s > 0; s >>= 1) { if (tid < s) r1[tid] += r1[tid + s]; __syncthreads(); }
    if (tid == 0) atomicAdd(&g_acc[4], (double)r1[0]);
    __syncthreads();
    r1[tid] = rmax; __syncthreads();
    for (int s = 128; s > 0; s >>= 1) { if (tid < s) r1[tid] = fmaxf(r1[tid], r1[tid + s]); __syncthreads(); }
    if (tid == 0) atomicAdd(&g_acc[5], (double)r1[0]);
}

// ---------------- finalize ----------------------------------------------------
__global__ void __launch_bounds__(256) finalize_kernel(float* __restrict__ out) {
    __shared__ float red[256];
    int tid = threadIdx.x;
    float s = 0.f;
    for (int j = tid; j < BSZ; j += 256) s += __int_as_float(g_colmax[j]);
    red[tid] = s; __syncthreads();
    for (int st = 128; st > 0; st >>= 1) { if (tid < st) red[tid] += red[tid + st]; __syncthreads(); }
    if (tid == 0) {
        float colsum = red[0];
        out[0] = (float)(g_acc[0] / 1024.0);                    // instance_loss
        out[1] = (float)(2.0 * g_acc[2] / 1024.0);              // global_align_loss
        out[2] = (float)(g_acc[1] / 1024.0);                    // cmpc_loss
        out[3] = (float)((g_acc[3] + g_acc[4]) / 1024.0);       // cmpm_loss
        out[4] = (float)(g_acc[5] + (double)colsum);            // mh_loss
        out[5] = (float)g_prec[0] / 1024.f;                     // visual_prec
        out[6] = (float)g_prec[1] / 1024.f;                     // textual_prec
    }
}

// ---------------- launch ------------------------------------------------------
extern "C" void kernel_launch(void* const* d_in, const int* in_sizes, int n_in,
                              void* d_out, int out_size) {
    const float* v      = (const float*)d_in[0];
    const float* t      = (const float*)d_in[1];
    const float* W      = (const float*)d_in[2];
    const float* W2     = (const float*)d_in[3];
    const int*   labels = (const int*)d_in[4];
    float* out = (float*)d_out;
    int C = in_sizes[2] / DD;   // 11003

    float *p_norm, *p_proj, *p_invW, *p_invW2, *p_l1, *p_l2;
    cudaGetSymbolAddress((void**)&p_norm,  g_norm);
    cudaGetSymbolAddress((void**)&p_proj,  g_proj);
    cudaGetSymbolAddress((void**)&p_invW,  g_invW);
    cudaGetSymbolAddress((void**)&p_invW2, g_invW2);
    cudaGetSymbolAddress((void**)&p_l1,    g_logits1);
    cudaGetSymbolAddress((void**)&p_l2,    g_logits2);

    init_kernel<<<4, 256>>>();
    hist_kernel<<<4, 256>>>(labels);
    normalize_kernel<<<2 * BSZ, 256>>>(v, t);
    proj_kernel<<<BSZ, 256>>>(v, t);
    colinv_kernel<<<(C + 255) / 256, 256>>>(W, 0, C);
    colinv_kernel<<<(C + 255) / 256, 256>>>(W2, 1, C);

    dim3 g1((C + 127) / 128, 2 * BSZ / 128);
    gemm_nn_tc<<<g1, 256>>>(p_norm, W,  p_invW,  28.f, p_l1, C);
    gemm_nn_tc<<<g1, 256>>>(p_proj, W2, p_invW2, 1.f,  p_l2, C);

    dim3 g2(BSZ / 128, BSZ / 128, 3);
    gemm_nt_tc<<<g2, 256>>>(v, t);

    diag_kernel<<<4, 256>>>();
    reduce_ce_kernel<<<4096, 256>>>(labels, C);
    pair_kernel<<<BSZ, 256>>>(labels);
    finalize_kernel<<<1, 256>>>(out);
}